// round 6
// baseline (speedup 1.0000x reference)
#include <cuda_runtime.h>

// Problem constants (fixed by the reference).
#define NB 4096
#define NT 512
#define NI 5
#define NH 16
#define FULLMASK 0xffffffffu

typedef unsigned long long ull;

// ---- fast activations ----
__device__ __forceinline__ float tanh_fast(float x) {
    float y;
    asm("tanh.approx.f32 %0, %1;" : "=f"(y) : "f"(x));
    return y;
}
__device__ __forceinline__ float sig_acc(float x) {   // epilogue only
    float e = __expf(-x);
    return __fdividef(1.0f, 1.0f + e);
}

// ---- packed f32x2 helpers (Blackwell FFMA2) ----
__device__ __forceinline__ ull pack2(float lo, float hi) {
    ull r;
    asm("mov.b64 %0, {%1, %2};" : "=l"(r) : "f"(lo), "f"(hi));
    return r;
}
__device__ __forceinline__ void unpack2(ull v, float& lo, float& hi) {
    asm("mov.b64 {%0, %1}, %2;" : "=f"(lo), "=f"(hi) : "l"(v));
}
__device__ __forceinline__ void fma2(ull& acc, ull a, ull b) {
    asm("fma.rn.f32x2 %0, %1, %2, %0;" : "+l"(acc) : "l"(a), "l"(b));
}
__device__ __forceinline__ ull add2(ull a, ull b) {
    ull r;
    asm("add.rn.f32x2 %0, %1, %2;" : "=l"(r) : "l"(a), "l"(b));
    return r;
}
__device__ __forceinline__ float hsum2(ull v) {
    float lo, hi;
    unpack2(v, lo, hi);
    return lo + hi;
}

// Single-warp LSTM over the ONLY batch row that matters (b = NB-1).
// NEW layout: state lane k (k = lane & 15) computes ALL FOUR gates for its
// own hidden index k. Zero cross-lane traffic except the (irreducible)
// h-broadcast via 16 pipelined shfl. Lanes 16..31 duplicate lanes 0..15.
// Sigmoid gates (i,f,o) have weights/biases pre-scaled by 0.5 so that
// sigmoid(x) = 0.5*tanh(scaled_sum) + 0.5 with no extra multiply on chain.
__global__ void __launch_bounds__(32, 1) lstm_last_row_kernel(
    const float* __restrict__ x,      // (B, T, I)
    const float* __restrict__ W_ih,   // (64, 5)
    const float* __restrict__ W_hh,   // (64, 16)
    const float* __restrict__ b_ih,   // (64,)
    const float* __restrict__ b_hh,   // (64,)
    const float* __restrict__ W_lin,  // (5, 16)
    const float* __restrict__ b_lin,  // (5,)
    float* __restrict__ out)          // (5,)
{
    __shared__ __align__(16) ull   xs2[NT * NI];  // x duplicated (v,v): 20 KB
    __shared__ __align__(16) float hfin[NH];      // final h for epilogue

    const int lane = threadIdx.x;

    // Stage x[B-1,:,:] as duplicated f32x2 pairs (ready fma2 operands).
    {
        const float4* src4 = reinterpret_cast<const float4*>(
            x + (size_t)(NB - 1) * NT * NI);
        #pragma unroll 4
        for (int i = lane; i < (NT * NI) / 4; i += 32) {
            const float4 v = src4[i];
            xs2[4 * i + 0] = pack2(v.x, v.x);
            xs2[4 * i + 1] = pack2(v.y, v.y);
            xs2[4 * i + 2] = pack2(v.z, v.z);
            xs2[4 * i + 3] = pack2(v.w, v.w);
        }
    }

    const int k  = lane & 15;     // hidden index owned by this lane
    const int ri = k;             // gate rows (PyTorch order i,f,g,o)
    const int rf = k + 16;
    const int rg = k + 32;
    const int ro = k + 48;

    // Recurrent weights, k-adjacent packed; 0.5 pre-scale on i,f,o rows.
    ull wi2[NH / 2], wf2[NH / 2], wg2[NH / 2], wo2[NH / 2];
    #pragma unroll
    for (int p = 0; p < NH / 2; ++p) {
        wi2[p] = pack2(0.5f * W_hh[ri * NH + 2 * p], 0.5f * W_hh[ri * NH + 2 * p + 1]);
        wf2[p] = pack2(0.5f * W_hh[rf * NH + 2 * p], 0.5f * W_hh[rf * NH + 2 * p + 1]);
        wg2[p] = pack2(       W_hh[rg * NH + 2 * p],        W_hh[rg * NH + 2 * p + 1]);
        wo2[p] = pack2(0.5f * W_hh[ro * NH + 2 * p], 0.5f * W_hh[ro * NH + 2 * p + 1]);
    }
    // Input-projection weights, gate-pair packed (i,f) and (g,o).
    ull wxif[NI], wxgo[NI];
    #pragma unroll
    for (int i = 0; i < NI; ++i) {
        wxif[i] = pack2(0.5f * W_ih[ri * NI + i], 0.5f * W_ih[rf * NI + i]);
        wxgo[i] = pack2(       W_ih[rg * NI + i], 0.5f * W_ih[ro * NI + i]);
    }
    const ull bif = pack2(0.5f * (b_ih[ri] + b_hh[ri]),
                          0.5f * (b_ih[rf] + b_hh[rf]));
    const ull bgo = pack2(       (b_ih[rg] + b_hh[rg]),
                          0.5f * (b_ih[ro] + b_hh[ro]));

    float h = 0.0f, c = 0.0f;

    __syncthreads();   // xs2 visible

    #pragma unroll 2
    for (int t = 0; t < NT; ++t) {
        const ull* xrow = &xs2[t * NI];

        // Input projection, packed gate-pairs (off-chain; fills bubbles).
        ull aif = bif, ago = bgo;
        #pragma unroll
        for (int i = 0; i < NI; ++i) {
            const ull xv = xrow[i];          // (x, x) duplicated
            fma2(aif, wxif[i], xv);
            fma2(ago, wxgo[i], xv);
        }
        float a_i, a_f, a_g, a_o;
        unpack2(aif, a_i, a_f);
        unpack2(ago, a_g, a_o);

        // h-broadcast: 16 pipelined shfl, packed into 8 (even,odd) pairs.
        ull hp[NH / 2];
        #pragma unroll
        for (int p = 0; p < NH / 2; ++p) {
            const float h0 = __shfl_sync(FULLMASK, h, 2 * p);
            const float h1 = __shfl_sync(FULLMASK, h, 2 * p + 1);
            hp[p] = pack2(h0, h1);
        }

        // Recurrent matvec: 32 fma2, 8 split chains (depth 4).
        ull ai0 = pack2(a_i, 0.0f), ai1 = pack2(0.0f, 0.0f);
        ull af0 = pack2(a_f, 0.0f), af1 = pack2(0.0f, 0.0f);
        ull ag0 = pack2(a_g, 0.0f), ag1 = pack2(0.0f, 0.0f);
        ull ao0 = pack2(a_o, 0.0f), ao1 = pack2(0.0f, 0.0f);
        #pragma unroll
        for (int p = 0; p < NH / 2; p += 2) {
            fma2(ai0, wi2[p], hp[p]);  fma2(ai1, wi2[p + 1], hp[p + 1]);
            fma2(af0, wf2[p], hp[p]);  fma2(af1, wf2[p + 1], hp[p + 1]);
            fma2(ag0, wg2[p], hp[p]);  fma2(ag1, wg2[p + 1], hp[p + 1]);
            fma2(ao0, wo2[p], hp[p]);  fma2(ao1, wo2[p + 1], hp[p + 1]);
        }
        const float Sg = hsum2(add2(ag0, ag1));   // g first: longest consumer
        const float Si = hsum2(add2(ai0, ai1));
        const float Sf = hsum2(add2(af0, af1));
        const float So = hsum2(add2(ao0, ao1));

        // Activations: 4 pipelined MUFU.TANH (i,f,o args pre-scaled).
        const float thg = tanh_fast(Sg);          // tanh(g)
        const float thi = tanh_fast(Si);          // -> sigmoid(i)
        const float thf = tanh_fast(Sf);          // -> sigmoid(f)
        const float tho = tanh_fast(So);          // -> sigmoid(o)

        const float si = fmaf(0.5f, thi, 0.5f);
        const float ig = si * thg;
        const float sf = fmaf(0.5f, thf, 0.5f);
        c = fmaf(sf, c, ig);
        const float tc = tanh_fast(c);
        const float so = fmaf(0.5f, tho, 0.5f);
        h = so * tc;
    }

    // Epilogue (off-chain, accurate math).
    if (lane < NH) hfin[lane] = h;
    __syncthreads();
    if (lane < 5) {
        float acc = b_lin[lane];
        #pragma unroll
        for (int j = 0; j < NH; ++j)
            acc = fmaf(W_lin[lane * NH + j], hfin[j], acc);
        out[lane] = sig_acc(acc);
    }
}

extern "C" void kernel_launch(void* const* d_in, const int* in_sizes, int n_in,
                              void* d_out, int out_size) {
    (void)in_sizes; (void)n_in; (void)out_size;
    const float* x     = (const float*)d_in[0];
    const float* W_ih  = (const float*)d_in[1];
    const float* W_hh  = (const float*)d_in[2];
    const float* b_ih  = (const float*)d_in[3];
    const float* b_hh  = (const float*)d_in[4];
    const float* W_lin = (const float*)d_in[5];
    const float* b_lin = (const float*)d_in[6];
    float* out = (float*)d_out;

    lstm_last_row_kernel<<<1, 32>>>(x, W_ih, W_hh, b_ih, b_hh, W_lin, b_lin, out);
}

// round 7
// speedup vs baseline: 1.1749x; 1.1749x over previous
#include <cuda_runtime.h>

// Problem constants (fixed by the reference).
#define NB 4096
#define NT 512
#define NI 5
#define NH 16
#define WND 32                  // xproj window (steps) per double-buffer half
#define NWND (NT / WND)         // 16 windows
#define FULLMASK 0xffffffffu

typedef unsigned long long ull;

// ---- fast activations ----
__device__ __forceinline__ float tanh_fast(float x) {
    float y;
    asm("tanh.approx.f32 %0, %1;" : "=f"(y) : "f"(x));
    return y;
}
__device__ __forceinline__ float sig_acc(float x) {   // epilogue only
    float e = __expf(-x);
    return __fdividef(1.0f, 1.0f + e);
}

// ---- packed f32x2 helpers (Blackwell FFMA2) ----
__device__ __forceinline__ ull pack2(float lo, float hi) {
    ull r;
    asm("mov.b64 %0, {%1, %2};" : "=l"(r) : "f"(lo), "f"(hi));
    return r;
}
__device__ __forceinline__ void unpack2(ull v, float& lo, float& hi) {
    asm("mov.b64 {%0, %1}, %2;" : "=f"(lo), "=f"(hi) : "l"(v));
}
__device__ __forceinline__ void fma2(ull& acc, ull a, ull b) {
    asm("fma.rn.f32x2 %0, %1, %2, %0;" : "+l"(acc) : "l"(a), "l"(b));
}
__device__ __forceinline__ ull mul2(ull a, ull b) {
    ull r;
    asm("mul.rn.f32x2 %0, %1, %2;" : "=l"(r) : "l"(a), "l"(b));
    return r;
}
__device__ __forceinline__ ull add2(ull a, ull b) {
    ull r;
    asm("add.rn.f32x2 %0, %1, %2;" : "=l"(r) : "l"(a), "l"(b));
    return r;
}
__device__ __forceinline__ float hsum2(ull v) {
    float lo, hi;
    unpack2(v, lo, hi);
    return lo + hi;
}

// Input-projection weights for one lane (warp 1 only).
struct XW {
    float wA[NI], wB[NI];
    float bA, bB;
};

// Warp 1: compute pre-activations (a0, a1) for one window of WND steps.
// dst[tl][lane] = float4(a0, 0, a1, 0)  -> warp 0 LDS.128 = ready acc inits.
__device__ __forceinline__ void fill_window(
    const XW& xw, const float* __restrict__ xs, float4* __restrict__ dst,
    int w, int lane)
{
    #pragma unroll 4
    for (int tl = 0; tl < WND; ++tl) {
        const float* xt = &xs[(w * WND + tl) * NI];
        float a0 = xw.bA, a1 = xw.bB;
        #pragma unroll
        for (int i = 0; i < NI; ++i) {
            const float xv = xt[i];          // broadcast LDS (N=1)
            a0 = fmaf(xw.wA[i], xv, a0);
            a1 = fmaf(xw.wB[i], xv, a1);
        }
        dst[tl * 32 + lane] = make_float4(a0, 0.0f, a1, 0.0f);
    }
}

// Two-warp LSTM over the ONLY batch row that matters (b = NB-1).
// Warp 0: serial recurrence, R2-proven comm structure (16-shfl h-broadcast,
//         2 shfl_down for f/o), sigmoid weights pre-scaled by 0.5.
// Warp 1: precomputes the input projection into a double-buffered window.
__global__ void __launch_bounds__(64, 1) lstm_last_row_kernel(
    const float* __restrict__ x,      // (B, T, I)
    const float* __restrict__ W_ih,   // (64, 5)
    const float* __restrict__ W_hh,   // (64, 16)
    const float* __restrict__ b_ih,   // (64,)
    const float* __restrict__ b_hh,   // (64,)
    const float* __restrict__ W_lin,  // (5, 16)
    const float* __restrict__ b_lin,  // (5,)
    float* __restrict__ out)          // (5,)
{
    __shared__ __align__(16) float  xs[NT * NI];        // 10 KB raw x row
    __shared__ __align__(16) float4 xp[2][WND * 32];    // 32 KB xproj windows
    __shared__ float hfin[NH];

    const int tid  = threadIdx.x;
    const int warp = tid >> 5;
    const int lane = tid & 31;

    // Cooperative stage of x[B-1,:,:] (both warps).
    {
        const float4* src4 = reinterpret_cast<const float4*>(
            x + (size_t)(NB - 1) * NT * NI);
        float4* dst4 = reinterpret_cast<float4*>(xs);
        #pragma unroll 4
        for (int i = tid; i < (NT * NI) / 4; i += 64) dst4[i] = src4[i];
    }

    // Gate rows (R2 mapping): g0 = lane -> i (lane<16) | f (lane>=16),
    //                         g1 = lane+32 -> g (lane<16) | o (lane>=16).
    const int g0 = lane;
    const int g1 = lane + 32;
    const float sB = (lane < 16) ? 1.0f : 0.5f;   // g full-scale, o pre-halved

    // Warp-1 state: input-projection weights (pre-scaled).
    XW xw;
    if (warp == 1) {
        #pragma unroll
        for (int i = 0; i < NI; ++i) {
            xw.wA[i] = 0.5f * W_ih[g0 * NI + i];
            xw.wB[i] = sB   * W_ih[g1 * NI + i];
        }
        xw.bA = 0.5f * (b_ih[g0] + b_hh[g0]);
        xw.bB = sB   * (b_ih[g1] + b_hh[g1]);
    }

    // Warp-0 state: recurrent weights, (even,odd)-packed, pre-scaled.
    ull wA2[NH / 2], wB2[NH / 2];
    if (warp == 0) {
        #pragma unroll
        for (int p = 0; p < NH / 2; ++p) {
            wA2[p] = pack2(0.5f * W_hh[g0 * NH + 2 * p],
                           0.5f * W_hh[g0 * NH + 2 * p + 1]);
            wB2[p] = pack2(sB * W_hh[g1 * NH + 2 * p],
                           sB * W_hh[g1 * NH + 2 * p + 1]);
        }
    }

    __syncthreads();   // xs staged

    // Prologue: warp 1 fills window 0 into buffer 0.
    if (warp == 1) fill_window(xw, xs, xp[0], 0, lane);
    __syncthreads();

    float h = 0.0f, c = 0.0f;

    for (int w = 0; w < NWND; ++w) {
        if (warp == 0) {
            const float4* buf = xp[w & 1];
            #pragma unroll 4
            for (int tl = 0; tl < WND; ++tl) {
                // Pre-activations: one LDS.128 -> (a0,0,a1,0) = acc inits.
                const float4 q = buf[tl * 32 + lane];
                ull accA0 = pack2(q.x, q.y);   // (a0, 0)
                ull accB0 = pack2(q.z, q.w);   // (a1, 0)

                // h-broadcast: 16 pipelined shfl -> 8 (even,odd) pairs.
                ull hp[NH / 2];
                #pragma unroll
                for (int p = 0; p < NH / 2; ++p) {
                    const float h0 = __shfl_sync(FULLMASK, h, 2 * p);
                    const float h1 = __shfl_sync(FULLMASK, h, 2 * p + 1);
                    hp[p] = pack2(h0, h1);
                }

                // Matvec: 16 packed ops, 4 split chains (mul2 first = no
                // zero-init movs).
                ull accA1 = mul2(wA2[1], hp[1]);
                ull accB1 = mul2(wB2[1], hp[1]);
                fma2(accA0, wA2[0], hp[0]);  fma2(accB0, wB2[0], hp[0]);
                fma2(accA0, wA2[2], hp[2]);  fma2(accB0, wB2[2], hp[2]);
                fma2(accA1, wA2[3], hp[3]);  fma2(accB1, wB2[3], hp[3]);
                fma2(accA0, wA2[4], hp[4]);  fma2(accB0, wB2[4], hp[4]);
                fma2(accA1, wA2[5], hp[5]);  fma2(accB1, wB2[5], hp[5]);
                fma2(accA0, wA2[6], hp[6]);  fma2(accB0, wB2[6], hp[6]);
                fma2(accA1, wA2[7], hp[7]);  fma2(accB1, wB2[7], hp[7]);

                const float SA = hsum2(add2(accA0, accA1)); // pre-scaled i|f
                const float SB = hsum2(add2(accB0, accB1)); // g | pre-scaled o

                // One MUFU.TANH per half (args already scaled).
                const float thA = tanh_fast(SA);   // -> sigmoid(i) | sigmoid(f)
                const float thB = tanh_fast(SB);   // tanh(g) | -> sigmoid(o)

                // Ship f/o tanh-halves to the state lanes.
                const float thF = __shfl_down_sync(FULLMASK, thA, 16);
                const float thO = __shfl_down_sync(FULLMASK, thB, 16);

                // Cell update (real state in lanes 0..15).
                const float si = fmaf(0.5f, thA, 0.5f);
                const float ig = si * thB;
                const float sf = fmaf(0.5f, thF, 0.5f);
                c = fmaf(sf, c, ig);
                const float tc = tanh_fast(c);
                const float so = fmaf(0.5f, thO, 0.5f);
                h = so * tc;
            }
        } else if (w + 1 < NWND) {
            fill_window(xw, xs, xp[(w + 1) & 1], w + 1, lane);
        }
        __syncthreads();
    }

    // Epilogue (off-chain, accurate math).
    if (warp == 0 && lane < NH) hfin[lane] = h;
    __syncthreads();
    if (tid < 5) {
        float acc = b_lin[tid];
        #pragma unroll
        for (int j = 0; j < NH; ++j)
            acc = fmaf(W_lin[tid * NH + j], hfin[j], acc);
        out[tid] = sig_acc(acc);
    }
}

extern "C" void kernel_launch(void* const* d_in, const int* in_sizes, int n_in,
                              void* d_out, int out_size) {
    (void)in_sizes; (void)n_in; (void)out_size;
    const float* x     = (const float*)d_in[0];
    const float* W_ih  = (const float*)d_in[1];
    const float* W_hh  = (const float*)d_in[2];
    const float* b_ih  = (const float*)d_in[3];
    const float* b_hh  = (const float*)d_in[4];
    const float* W_lin = (const float*)d_in[5];
    const float* b_lin = (const float*)d_in[6];
    float* out = (float*)d_out;

    lstm_last_row_kernel<<<1, 64>>>(x, W_ih, W_hh, b_ih, b_hh, W_lin, b_lin, out);
}